// round 14
// baseline (speedup 1.0000x reference)
#include <cuda_runtime.h>
#include <math.h>

#define NB   16
#define NCI  512
#define NCO  128
#define LAMBDA 0.2f
#define INV_SQRT2PI 0.39894228040143267794f
// -0.5 * log2(e)
#define NEG_HALF_LOG2E -0.72134752044448170367f
#define PADV 68

__device__ float g_logits[NB * NCO];
__device__ unsigned g_ctr = 0;

typedef unsigned long long u64;
union F4 { float4 f; u64 d[2]; float s[4]; };

__device__ __forceinline__ u64 pk2(float lo, float hi) {
    u64 r; asm("mov.b64 %0,{%1,%2};" : "=l"(r) : "f"(lo), "f"(hi)); return r;
}
__device__ __forceinline__ void up2(u64 v, float& lo, float& hi) {
    asm("mov.b64 {%0,%1},%2;" : "=f"(lo), "=f"(hi) : "l"(v));
}
__device__ __forceinline__ u64 fma2(u64 a, u64 b, u64 c) {
    u64 d; asm("fma.rn.f32x2 %0,%1,%2,%3;" : "=l"(d) : "l"(a), "l"(b), "l"(c)); return d;
}
__device__ __forceinline__ u64 mul2(u64 a, u64 b) {
    u64 d; asm("mul.rn.f32x2 %0,%1,%2;" : "=l"(d) : "l"(a), "l"(b)); return d;
}
__device__ __forceinline__ u64 add2(u64 a, u64 b) {
    u64 d; asm("add.rn.f32x2 %0,%1,%2;" : "=l"(d) : "l"(a), "l"(b)); return d;
}
__device__ __forceinline__ unsigned smem_u32(const void* p) {
    return (unsigned)__cvta_generic_to_shared(p);
}
__device__ __forceinline__ unsigned mapa_u32(unsigned addr, unsigned rank) {
    unsigned r;
    asm("mapa.shared::cluster.u32 %0, %1, %2;" : "=r"(r) : "r"(addr), "r"(rank));
    return r;
}
__device__ __forceinline__ void st_cluster_f32(unsigned addr, float v) {
    asm volatile("st.shared::cluster.f32 [%0], %1;" :: "r"(addr), "f"(v) : "memory");
}
__device__ __forceinline__ void cluster_sync_() {
    asm volatile("barrier.cluster.arrive.aligned;" ::: "memory");
    asm volatile("barrier.cluster.wait.aligned;" ::: "memory");
}

// ---------------------------------------------------------------------------
// Cluster-split fused EM routing, v2: no smem staging (pose/trans read
// gmem->regs, L2-resident), V in smem in s-major slot order (slot = s*8+q),
// W folded into the stats exchange (3 cluster syncs total), phase
// double-buffered exchange buffers.
// ---------------------------------------------------------------------------
__global__ void __launch_bounds__(512, 2) __cluster_dims__(2, 1, 1)
k_fused(const float* __restrict__ act, const float* __restrict__ pose,
        const float* __restrict__ trans, const float* __restrict__ ba,
        const float* __restrict__ bb, float* __restrict__ out)
{
    extern __shared__ float sh[];
    float* Vs   = sh;                    // [256*68] votes, slot-major s*8+q
    float* pw   = Vs + 256 * PADV;       // [512] e-step partial prob sums
    float* acts = pw + 512;              // [256]
    float* Sp1  = acts + 256;            // [16*64]
    float* Sp2  = Sp1 + 1024;            // [16*64]
    float* wsl  = Sp2 + 1024;            // [16] per-warp W partials
    float* mus  = wsl + 16;              // [64]
    float* nm   = mus + 64;              // [64]
    float* Aa   = nm + 64;               // [64]
    float* Cc   = Aa + 64;               // [64]
    float* xS1  = Cc + 64;               // [2 phases][2 ranks][64]
    float* xS2  = xS1 + 256;             // [2][2][64]
    float* xW   = xS2 + 256;             // [2][2]
    float* misc = xW + 4;                // [4]: 0 lsum, 1 flag

    const unsigned rank = blockIdx.x;    // cluster rank (cluster dims (2,1,1))
    const int co = blockIdx.y, b = blockIdx.z;
    const int t = threadIdx.x, lane = t & 31, wid = t >> 5;
    const int tq = t & 15, trow = t >> 4;
    const int cil = t & 255, sh2 = t >> 8;

    if (t < 256) acts[t] = act[b * NCI + (int)rank * 256 + t];
    if (t < 4) misc[t] = 0.f;

    // ---- V generation: gmem -> regs -> smem. Thread owns (ci, s-half). ----
    {
        const int gci = (int)rank * 256 + cil;
        const float* pb = pose + ((size_t)(b * NCI + gci)) * 64;
        const float* tb = trans + ((size_t)gci * NCO + co) * 64 + sh2 * 4;
        u64 acc[16];                      // [qpair 0..3][s 0..3]
        #pragma unroll
        for (int i = 0; i < 16; i++) acc[i] = 0ull;
        #pragma unroll 2
        for (int p = 0; p < 8; p++) {
            F4 p0; p0.f = *(const float4*)(pb + p * 8);       // q0..3 pairs
            F4 p1; p1.f = *(const float4*)(pb + p * 8 + 4);   // q4..7 pairs
            const float4 tv = *(const float4*)(tb + p * 8);   // s0..3 (this half)
            const u64 t0 = pk2(tv.x, tv.x), t1 = pk2(tv.y, tv.y);
            const u64 t2 = pk2(tv.z, tv.z), t3 = pk2(tv.w, tv.w);
            acc[0]  = fma2(p0.d[0], t0, acc[0]);  acc[1]  = fma2(p0.d[0], t1, acc[1]);
            acc[2]  = fma2(p0.d[0], t2, acc[2]);  acc[3]  = fma2(p0.d[0], t3, acc[3]);
            acc[4]  = fma2(p0.d[1], t0, acc[4]);  acc[5]  = fma2(p0.d[1], t1, acc[5]);
            acc[6]  = fma2(p0.d[1], t2, acc[6]);  acc[7]  = fma2(p0.d[1], t3, acc[7]);
            acc[8]  = fma2(p1.d[0], t0, acc[8]);  acc[9]  = fma2(p1.d[0], t1, acc[9]);
            acc[10] = fma2(p1.d[0], t2, acc[10]); acc[11] = fma2(p1.d[0], t3, acc[11]);
            acc[12] = fma2(p1.d[1], t0, acc[12]); acc[13] = fma2(p1.d[1], t1, acc[13]);
            acc[14] = fma2(p1.d[1], t2, acc[14]); acc[15] = fma2(p1.d[1], t3, acc[15]);
        }
        // slot = (sh2*4 + s)*8 + q  (s-major)
        float* vrow = Vs + cil * PADV + sh2 * 32;
        #pragma unroll
        for (int s = 0; s < 4; s++) {
            F4 lo; lo.d[0] = acc[s];     lo.d[1] = acc[4 + s];   // q0..3
            F4 hi; hi.d[0] = acc[8 + s]; hi.d[1] = acc[12 + s];  // q4..7
            *(float4*)(vrow + s * 8)     = lo.f;
            *(float4*)(vrow + s * 8 + 4) = hi.f;
        }
    }
    __syncthreads();

    float v8[8]; float wacc;

    // ---- m-step: thread (tq,trow) accumulates 4-slot stats over 8 ci ----
    #define M_STEP(FIRST)                                                       \
    {                                                                           \
        u64 nm0 = 0ull, nm1 = 0ull;                                             \
        if (!(FIRST)) {                                                         \
            const float4 m0v = *(const float4*)(mus + tq * 4);                  \
            nm0 = pk2(-m0v.x, -m0v.y); nm1 = pk2(-m0v.z, -m0v.w);               \
        }                                                                       \
        u64 s1a = 0ull, s1b = 0ull, s2a = 0ull, s2b = 0ull;                     \
        wacc = 0.f;                                                             \
        _Pragma("unroll 4")                                                     \
        for (int i = 0; i < 8; i++) {                                           \
            const int lci = i * 32 + trow;                                      \
            const float w = (FIRST) ? acts[lci]                                 \
                                    : acts[lci] * (pw[lci] + pw[256 + lci]);    \
            wacc += w;                                                          \
            F4 v; v.f = *(const float4*)(Vs + lci * PADV + tq * 4);             \
            const u64 vs0 = add2(v.d[0], nm0), vs1 = add2(v.d[1], nm1);         \
            const u64 r2 = pk2(w, w);                                           \
            const u64 rv0 = mul2(r2, vs0), rv1 = mul2(r2, vs1);                 \
            s1a = add2(s1a, rv0); s1b = add2(s1b, rv1);                         \
            s2a = fma2(rv0, vs0, s2a); s2b = fma2(rv1, vs1, s2b);               \
        }                                                                       \
        up2(s1a, v8[0], v8[1]); up2(s1b, v8[2], v8[3]);                         \
        up2(s2a, v8[4], v8[5]); up2(s2b, v8[6], v8[7]);                         \
    }

    // ---- stats + W reduce + cluster exchange (phase double-buffered) ----
    #define REDUCE_STATS(PH, M0_EXPR, FINAL)                                    \
    {                                                                           \
        _Pragma("unroll")                                                       \
        for (int j = 0; j < 8; j++)                                             \
            v8[j] += __shfl_xor_sync(0xffffffffu, v8[j], 16);                   \
        wacc += __shfl_xor_sync(0xffffffffu, wacc, 16);                         \
        if (lane < 16) {                                                        \
            *(float4*)(Sp1 + wid * 64 + lane * 4) =                             \
                make_float4(v8[0], v8[1], v8[2], v8[3]);                        \
            *(float4*)(Sp2 + wid * 64 + lane * 4) =                             \
                make_float4(v8[4], v8[5], v8[6], v8[7]);                        \
        }                                                                       \
        if (lane == 0) wsl[wid] = wacc;                                         \
        __syncthreads();                                                        \
        if (t < 64) {                                                           \
            float s1 = 0.f, s2 = 0.f;                                           \
            _Pragma("unroll")                                                   \
            for (int ww = 0; ww < 16; ww++) {                                   \
                s1 += Sp1[ww * 64 + t];                                         \
                s2 += Sp2[ww * 64 + t];                                         \
            }                                                                   \
            float* p1 = xS1 + (PH) * 128 + (int)rank * 64 + t;                  \
            float* p2 = xS2 + (PH) * 128 + (int)rank * 64 + t;                  \
            *p1 = s1; *p2 = s2;                                                 \
            st_cluster_f32(mapa_u32(smem_u32(p1), rank ^ 1u), s1);              \
            st_cluster_f32(mapa_u32(smem_u32(p2), rank ^ 1u), s2);              \
        }                                                                       \
        if (t == 0) {                                                           \
            float Wr = 0.f;                                                     \
            _Pragma("unroll")                                                   \
            for (int ww = 0; ww < 16; ww++) Wr += wsl[ww];                      \
            float* pq = xW + (PH) * 2 + (int)rank;                              \
            *pq = Wr;                                                           \
            st_cluster_f32(mapa_u32(smem_u32(pq), rank ^ 1u), Wr);              \
        }                                                                       \
        cluster_sync_();                                                        \
        if (t < 64) {                                                           \
            const float s1 = xS1[(PH)*128 + t] + xS1[(PH)*128 + 64 + t];        \
            const float s2 = xS2[(PH)*128 + t] + xS2[(PH)*128 + 64 + t];        \
            const float invW = 1.f / (xW[(PH)*2] + xW[(PH)*2 + 1]);             \
            const float m0 = (M0_EXPR);                                         \
            const float dd = s1 * invW;                                         \
            const float mu = m0 + dd;                                           \
            const float var = fmaxf(s2 * invW - dd * dd, 1e-30f);               \
            mus[t] = mu;                                                        \
            nm[t] = -mu;                                                        \
            Aa[t] = NEG_HALF_LOG2E / var;                                       \
            Cc[t] = INV_SQRT2PI * rsqrtf(var);                                  \
            if (FINAL) {                                                        \
                if (rank == 0)  /* slot t = s*8+q -> original index q*8+s */    \
                    out[NB * NCO + ((size_t)(b * NCO + co)) * 64                \
                        + ((t & 7) * 8 + (t >> 3))] = mu;                       \
                float l = 0.5f * logf(var);                                     \
                _Pragma("unroll")                                               \
                for (int o = 16; o; o >>= 1)                                    \
                    l += __shfl_xor_sync(0xffffffffu, l, o);                    \
                if (lane == 0) atomicAdd(&misc[0], l);                          \
            }                                                                   \
        }                                                                       \
        __syncthreads();                                                        \
    }

    // ---- e-step: thread owns (ci, s-half); unnormalized prob sums ----
    #define E_STEP()                                                            \
    {                                                                           \
        const int cb = sh2 * 32;                                                \
        const float* Vb = Vs + cil * PADV + cb;                                 \
        float accp = 0.f;                                                       \
        _Pragma("unroll 4")                                                     \
        for (int j = 0; j < 8; j++) {                                           \
            F4 v;  v.f  = *(const float4*)(Vb + j * 4);                         \
            F4 nv; nv.f = *(const float4*)(nm + cb + j * 4);                    \
            F4 Av; Av.f = *(const float4*)(Aa + cb + j * 4);                    \
            F4 Cv; Cv.f = *(const float4*)(Cc + cb + j * 4);                    \
            const u64 d0 = add2(v.d[0], nv.d[0]);                               \
            const u64 d1 = add2(v.d[1], nv.d[1]);                               \
            const u64 e0 = mul2(Av.d[0], mul2(d0, d0));                         \
            const u64 e1 = mul2(Av.d[1], mul2(d1, d1));                         \
            float a0, a1, a2, a3; up2(e0, a0, a1); up2(e1, a2, a3);             \
            accp = fmaf(Cv.s[0], exp2f(a0), accp);                              \
            accp = fmaf(Cv.s[1], exp2f(a1), accp);                              \
            accp = fmaf(Cv.s[2], exp2f(a2), accp);                              \
            accp = fmaf(Cv.s[3], exp2f(a3), accp);                              \
        }                                                                       \
        pw[sh2 * 256 + cil] = accp;                                             \
        __syncthreads();                                                        \
    }

    M_STEP(1)
    REDUCE_STATS(0, 0.f, 0)            // m1 (W = sum(act) exchanged in-reduce)
    E_STEP()
    M_STEP(0)
    REDUCE_STATS(1, mus[t], 0)         // m2 (shifted variance)
    E_STEP()
    M_STEP(0)
    REDUCE_STATS(0, mus[t], 1)         // m3 -> mu out + logit sum

    // ---- logits + counter-fused final softmax (rank-0 CTAs only) ----
    if (rank == 0) {
        if (t == 0) {
            g_logits[b * NCO + co] = LAMBDA * (ba[co] - bb[co] - misc[0]);
            __threadfence();
            unsigned done = atomicAdd(&g_ctr, 1u);
            misc[1] = (done == (unsigned)(NB * NCO - 1)) ? 1.f : 0.f;
        }
        __syncthreads();
        if (misc[1] != 0.f) {
            __threadfence();
            float x0 = g_logits[wid * NCO + lane * 4 + 0];
            float x1 = g_logits[wid * NCO + lane * 4 + 1];
            float x2 = g_logits[wid * NCO + lane * 4 + 2];
            float x3 = g_logits[wid * NCO + lane * 4 + 3];
            float m = fmaxf(fmaxf(x0, x1), fmaxf(x2, x3));
            #pragma unroll
            for (int o = 16; o; o >>= 1)
                m = fmaxf(m, __shfl_xor_sync(0xffffffffu, m, o));
            const float e0 = __expf(x0 - m), e1 = __expf(x1 - m);
            const float e2 = __expf(x2 - m), e3 = __expf(x3 - m);
            float s = (e0 + e1) + (e2 + e3);
            #pragma unroll
            for (int o = 16; o; o >>= 1)
                s += __shfl_xor_sync(0xffffffffu, s, o);
            const float inv = 1.f / s;
            out[wid * NCO + lane * 4 + 0] = e0 * inv;
            out[wid * NCO + lane * 4 + 1] = e1 * inv;
            out[wid * NCO + lane * 4 + 2] = e2 * inv;
            out[wid * NCO + lane * 4 + 3] = e3 * inv;
            if (t == 0) g_ctr = 0;       // reset for next graph replay
        }
    }
}

// ---------------------------------------------------------------------------
extern "C" void kernel_launch(void* const* d_in, const int* in_sizes, int n_in,
                              void* d_out, int out_size)
{
    const float* act   = (const float*)d_in[0];
    const float* pose  = (const float*)d_in[1];
    const float* trans = (const float*)d_in[2];
    const float* ba    = (const float*)d_in[3];
    const float* bb    = (const float*)d_in[4];
    float* out = (float*)d_out;

    // floats: Vs 17408 + pw 512 + acts 256 + Sp 2048 + wsl 16 + consts 256
    //         + xS 512 + xW 4 + misc 4 = 21016  (~84 KB -> 2 CTAs/SM)
    const int smem = (256 * PADV + 512 + 256 + 2048 + 16 + 256 + 512 + 4 + 4)
                     * (int)sizeof(float);
    cudaFuncSetAttribute(k_fused, cudaFuncAttributeMaxDynamicSharedMemorySize, smem);

    dim3 grid(2, NCO, NB);               // cluster (2,1,1) over grid.x
    k_fused<<<grid, 512, smem>>>(act, pose, trans, ba, bb, out);
}

// round 16
// speedup vs baseline: 1.5483x; 1.5483x over previous
#include <cuda_runtime.h>
#include <math.h>

#define NB   16
#define NCI  512
#define NCO  128
#define LAMBDA 0.2f
#define INV_SQRT2PI 0.39894228040143267794f
// -0.5 * log2(e)
#define NEG_HALF_LOG2E -0.72134752044448170367f
#define PADV 68
#define PADS 72

__device__ float g_logits[NB * NCO];
__device__ unsigned g_ctr = 0;

typedef unsigned long long u64;
union F4 { float4 f; u64 d[2]; float s[4]; };
union F2 { float2 f; u64 d; float s[2]; };

__device__ __forceinline__ u64 pk2(float lo, float hi) {
    u64 r; asm("mov.b64 %0,{%1,%2};" : "=l"(r) : "f"(lo), "f"(hi)); return r;
}
__device__ __forceinline__ void up2(u64 v, float& lo, float& hi) {
    asm("mov.b64 {%0,%1},%2;" : "=f"(lo), "=f"(hi) : "l"(v));
}
__device__ __forceinline__ u64 fma2(u64 a, u64 b, u64 c) {
    u64 d; asm("fma.rn.f32x2 %0,%1,%2,%3;" : "=l"(d) : "l"(a), "l"(b), "l"(c)); return d;
}
__device__ __forceinline__ u64 mul2(u64 a, u64 b) {
    u64 d; asm("mul.rn.f32x2 %0,%1,%2;" : "=l"(d) : "l"(a), "l"(b)); return d;
}
__device__ __forceinline__ u64 add2(u64 a, u64 b) {
    u64 d; asm("add.rn.f32x2 %0,%1,%2;" : "=l"(d) : "l"(a), "l"(b)); return d;
}
__device__ __forceinline__ void cp16(void* smem, const void* g) {
    unsigned s = (unsigned)__cvta_generic_to_shared(smem);
    asm volatile("cp.async.cg.shared.global [%0], [%1], 16;" :: "r"(s), "l"(g));
}
__device__ __forceinline__ unsigned smem_u32(const void* p) {
    return (unsigned)__cvta_generic_to_shared(p);
}
__device__ __forceinline__ unsigned mapa_u32(unsigned addr, unsigned rank) {
    unsigned r;
    asm("mapa.shared::cluster.u32 %0, %1, %2;" : "=r"(r) : "r"(addr), "r"(rank));
    return r;
}
__device__ __forceinline__ void st_cluster_f32(unsigned addr, float v) {
    asm volatile("st.shared::cluster.f32 [%0], %1;" :: "r"(addr), "f"(v) : "memory");
}
__device__ __forceinline__ void cluster_sync_() {
    asm volatile("barrier.cluster.arrive.aligned;" ::: "memory");
    asm volatile("barrier.cluster.wait.aligned;" ::: "memory");
}

// ---------------------------------------------------------------------------
// Cluster-split fused EM routing, v3: coalesced cp.async staging (single
// 64-ci chunk buffer) + 8-slot-per-thread V-gen (1 LDS.128 + 1 LDS.64 per
// 4 FFMA2), slot-major V (slot = s*8+q), folded-W exchange (3 cluster syncs).
// ---------------------------------------------------------------------------
__global__ void __launch_bounds__(512, 2) __cluster_dims__(2, 1, 1)
k_fused(const float* __restrict__ act, const float* __restrict__ pose,
        const float* __restrict__ trans, const float* __restrict__ ba,
        const float* __restrict__ bb, float* __restrict__ out)
{
    extern __shared__ float sh[];
    float* Ps   = sh;                    // [64*72] pose staging (per chunk)
    float* Ts   = Ps + 64 * PADS;        // [64*72] trans staging
    float* Sp1  = sh;                    // alias (dead after V-gen): [16*64]
    float* Sp2  = sh + 1024;             // alias: [16*64]
    float* pw   = sh + 2048;             // alias: [512] e-step partials
    float* Vs   = Ts + 64 * PADS;        // [256*68] votes, slot-major s*8+q
    float* acts = Vs + 256 * PADV;       // [256]
    float* wsl  = acts + 256;            // [16] per-warp W partials
    float* mus  = wsl + 16;              // [64]
    float* nm   = mus + 64;              // [64]
    float* Aa   = nm + 64;               // [64]
    float* Cc   = Aa + 64;               // [64]
    float* xS1  = Cc + 64;               // [2 phases][2 ranks][64]
    float* xS2  = xS1 + 256;             // [2][2][64]
    float* xW   = xS2 + 256;             // [2][2]
    float* misc = xW + 4;                // [4]: 0 lsum, 1 flag

    const unsigned rank = blockIdx.x;    // cluster rank (cluster (2,1,1))
    const int co = blockIdx.y, b = blockIdx.z;
    const int t = threadIdx.x, lane = t & 31, wid = t >> 5;
    const int tq = t & 15, trow = t >> 4;
    const int cil = t & 255, sh2 = t >> 8;

    auto stage = [&](int c) {            // stage 64 rows of pose+trans
        #pragma unroll
        for (int j = 0; j < 2; j++) {
            const int idx = j * 512 + t;
            const int row = idx >> 4, f4 = (idx & 15) << 2;
            const int gci = (int)rank * 256 + c * 64 + row;
            cp16(Ps + row * PADS + f4, pose + ((size_t)(b * NCI + gci)) * 64 + f4);
            cp16(Ts + row * PADS + f4, trans + ((size_t)gci * NCO + co) * 64 + f4);
        }
        asm volatile("cp.async.commit_group;" ::: "memory");
    };

    if (t < 256) acts[t] = act[b * NCI + (int)rank * 256 + t];
    if (t < 4) misc[t] = 0.f;
    stage(0);

    // ---- V generation: thread = (ci-local 0..63, sg 0..7); sg = (sq, qh);
    //      per p: 1 pose LDS.128 (4 q) + 1 trans LDS.64 (2 s) -> 4 FFMA2. ----
    {
        const int vci = t >> 3;            // 0..63 within chunk
        const int sg = t & 7, qh = sg & 1, sq = sg >> 1;
        for (int c = 0; c < 4; c++) {
            asm volatile("cp.async.wait_group 0;" ::: "memory");
            __syncthreads();
            const float* pr = Ps + vci * PADS + qh * 4;
            const float* tr = Ts + vci * PADS + sq * 2;
            u64 a00 = 0ull, a10 = 0ull, a01 = 0ull, a11 = 0ull;
            #pragma unroll
            for (int p = 0; p < 8; p++) {
                F4 pv; pv.f = *(const float4*)(pr + p * 8);   // q qh*4..+3 (2 pairs)
                F2 tv; tv.f = *(const float2*)(tr + p * 8);   // s sq*2, sq*2+1
                const u64 t0 = pk2(tv.s[0], tv.s[0]);
                const u64 t1 = pk2(tv.s[1], tv.s[1]);
                a00 = fma2(pv.d[0], t0, a00); a10 = fma2(pv.d[1], t0, a10);
                a01 = fma2(pv.d[0], t1, a01); a11 = fma2(pv.d[1], t1, a11);
            }
            float* vrow = Vs + (c * 64 + vci) * PADV + qh * 4;
            F4 w0; w0.d[0] = a00; w0.d[1] = a10;
            F4 w1; w1.d[0] = a01; w1.d[1] = a11;
            *(float4*)(vrow + (sq * 2) * 8)     = w0.f;       // slot s*8+q
            *(float4*)(vrow + (sq * 2 + 1) * 8) = w1.f;
            __syncthreads();                 // staging consumed; safe to refill
            if (c < 3) stage(c + 1);
        }
    }

    float v8[8]; float wacc;

    // ---- m-step: thread (tq,trow) accumulates 4-slot stats over 8 ci ----
    #define M_STEP(FIRST)                                                       \
    {                                                                           \
        u64 nm0 = 0ull, nm1 = 0ull;                                             \
        if (!(FIRST)) {                                                         \
            const float4 m0v = *(const float4*)(mus + tq * 4);                  \
            nm0 = pk2(-m0v.x, -m0v.y); nm1 = pk2(-m0v.z, -m0v.w);               \
        }                                                                       \
        u64 s1a = 0ull, s1b = 0ull, s2a = 0ull, s2b = 0ull;                     \
        wacc = 0.f;                                                             \
        _Pragma("unroll 4")                                                     \
        for (int i = 0; i < 8; i++) {                                           \
            const int lci = i * 32 + trow;                                      \
            const float w = (FIRST) ? acts[lci]                                 \
                                    : acts[lci] * (pw[lci] + pw[256 + lci]);    \
            wacc += w;                                                          \
            F4 v; v.f = *(const float4*)(Vs + lci * PADV + tq * 4);             \
            const u64 vs0 = add2(v.d[0], nm0), vs1 = add2(v.d[1], nm1);         \
            const u64 r2 = pk2(w, w);                                           \
            const u64 rv0 = mul2(r2, vs0), rv1 = mul2(r2, vs1);                 \
            s1a = add2(s1a, rv0); s1b = add2(s1b, rv1);                         \
            s2a = fma2(rv0, vs0, s2a); s2b = fma2(rv1, vs1, s2b);               \
        }                                                                       \
        up2(s1a, v8[0], v8[1]); up2(s1b, v8[2], v8[3]);                         \
        up2(s2a, v8[4], v8[5]); up2(s2b, v8[6], v8[7]);                         \
    }

    // ---- stats + W reduce + cluster exchange (phase double-buffered) ----
    #define REDUCE_STATS(PH, M0_EXPR, FINAL)                                    \
    {                                                                           \
        _Pragma("unroll")                                                       \
        for (int j = 0; j < 8; j++)                                             \
            v8[j] += __shfl_xor_sync(0xffffffffu, v8[j], 16);                   \
        wacc += __shfl_xor_sync(0xffffffffu, wacc, 16);                         \
        if (lane < 16) {                                                        \
            *(float4*)(Sp1 + wid * 64 + lane * 4) =                             \
                make_float4(v8[0], v8[1], v8[2], v8[3]);                        \
            *(float4*)(Sp2 + wid * 64 + lane * 4) =                             \
                make_float4(v8[4], v8[5], v8[6], v8[7]);                        \
        }                                                                       \
        if (lane == 0) wsl[wid] = wacc;                                         \
        __syncthreads();                                                        \
        if (t < 64) {                                                           \
            float s1 = 0.f, s2 = 0.f;                                           \
            _Pragma("unroll")                                                   \
            for (int ww = 0; ww < 16; ww++) {                                   \
                s1 += Sp1[ww * 64 + t];                                         \
                s2 += Sp2[ww * 64 + t];                                         \
            }                                                                   \
            float* p1 = xS1 + (PH) * 128 + (int)rank * 64 + t;                  \
            float* p2 = xS2 + (PH) * 128 + (int)rank * 64 + t;                  \
            *p1 = s1; *p2 = s2;                                                 \
            st_cluster_f32(mapa_u32(smem_u32(p1), rank ^ 1u), s1);              \
            st_cluster_f32(mapa_u32(smem_u32(p2), rank ^ 1u), s2);              \
        }                                                                       \
        if (t == 0) {                                                           \
            float Wr = 0.f;                                                     \
            _Pragma("unroll")                                                   \
            for (int ww = 0; ww < 16; ww++) Wr += wsl[ww];                      \
            float* pq = xW + (PH) * 2 + (int)rank;                              \
            *pq = Wr;                                                           \
            st_cluster_f32(mapa_u32(smem_u32(pq), rank ^ 1u), Wr);              \
        }                                                                       \
        cluster_sync_();                                                        \
        if (t < 64) {                                                           \
            const float s1 = xS1[(PH)*128 + t] + xS1[(PH)*128 + 64 + t];        \
            const float s2 = xS2[(PH)*128 + t] + xS2[(PH)*128 + 64 + t];        \
            const float invW = 1.f / (xW[(PH)*2] + xW[(PH)*2 + 1]);             \
            const float m0 = (M0_EXPR);                                         \
            const float dd = s1 * invW;                                         \
            const float mu = m0 + dd;                                           \
            const float var = fmaxf(s2 * invW - dd * dd, 1e-30f);               \
            mus[t] = mu;                                                        \
            nm[t] = -mu;                                                        \
            Aa[t] = NEG_HALF_LOG2E / var;                                       \
            Cc[t] = INV_SQRT2PI * rsqrtf(var);                                  \
            if (FINAL) {                                                        \
                if (rank == 0)  /* slot t = s*8+q -> original index q*8+s */    \
                    out[NB * NCO + ((size_t)(b * NCO + co)) * 64                \
                        + ((t & 7) * 8 + (t >> 3))] = mu;                       \
                float l = 0.5f * logf(var);                                     \
                _Pragma("unroll")                                               \
                for (int o = 16; o; o >>= 1)                                    \
                    l += __shfl_xor_sync(0xffffffffu, l, o);                    \
                if (lane == 0) atomicAdd(&misc[0], l);                          \
            }                                                                   \
        }                                                                       \
        __syncthreads();                                                        \
    }

    // ---- e-step: thread owns (ci, s-half); unnormalized prob sums ----
    #define E_STEP()                                                            \
    {                                                                           \
        const int cb = sh2 * 32;                                                \
        const float* Vb = Vs + cil * PADV + cb;                                 \
        float accp = 0.f;                                                       \
        _Pragma("unroll 4")                                                     \
        for (int j = 0; j < 8; j++) {                                           \
            F4 v;  v.f  = *(const float4*)(Vb + j * 4);                         \
            F4 nv; nv.f = *(const float4*)(nm + cb + j * 4);                    \
            F4 Av; Av.f = *(const float4*)(Aa + cb + j * 4);                    \
            F4 Cv; Cv.f = *(const float4*)(Cc + cb + j * 4);                    \
            const u64 d0 = add2(v.d[0], nv.d[0]);                               \
            const u64 d1 = add2(v.d[1], nv.d[1]);                               \
            const u64 e0 = mul2(Av.d[0], mul2(d0, d0));                         \
            const u64 e1 = mul2(Av.d[1], mul2(d1, d1));                         \
            float a0, a1, a2, a3; up2(e0, a0, a1); up2(e1, a2, a3);             \
            accp = fmaf(Cv.s[0], exp2f(a0), accp);                              \
            accp = fmaf(Cv.s[1], exp2f(a1), accp);                              \
            accp = fmaf(Cv.s[2], exp2f(a2), accp);                              \
            accp = fmaf(Cv.s[3], exp2f(a3), accp);                              \
        }                                                                       \
        pw[sh2 * 256 + cil] = accp;                                             \
        __syncthreads();                                                        \
    }

    M_STEP(1)
    REDUCE_STATS(0, 0.f, 0)            // m1 (W = sum(act) exchanged in-reduce)
    E_STEP()
    M_STEP(0)
    REDUCE_STATS(1, mus[t], 0)         // m2 (shifted variance)
    E_STEP()
    M_STEP(0)
    REDUCE_STATS(0, mus[t], 1)         // m3 -> mu out + logit sum

    // ---- logits + counter-fused final softmax (rank-0 CTAs only) ----
    if (rank == 0) {
        if (t == 0) {
            g_logits[b * NCO + co] = LAMBDA * (ba[co] - bb[co] - misc[0]);
            __threadfence();
            unsigned done = atomicAdd(&g_ctr, 1u);
            misc[1] = (done == (unsigned)(NB * NCO - 1)) ? 1.f : 0.f;
        }
        __syncthreads();
        if (misc[1] != 0.f) {
            __threadfence();
            float x0 = g_logits[wid * NCO + lane * 4 + 0];
            float x1 = g_logits[wid * NCO + lane * 4 + 1];
            float x2 = g_logits[wid * NCO + lane * 4 + 2];
            float x3 = g_logits[wid * NCO + lane * 4 + 3];
            float m = fmaxf(fmaxf(x0, x1), fmaxf(x2, x3));
            #pragma unroll
            for (int o = 16; o; o >>= 1)
                m = fmaxf(m, __shfl_xor_sync(0xffffffffu, m, o));
            const float e0 = __expf(x0 - m), e1 = __expf(x1 - m);
            const float e2 = __expf(x2 - m), e3 = __expf(x3 - m);
            float s = (e0 + e1) + (e2 + e3);
            #pragma unroll
            for (int o = 16; o; o >>= 1)
                s += __shfl_xor_sync(0xffffffffu, s, o);
            const float inv = 1.f / s;
            out[wid * NCO + lane * 4 + 0] = e0 * inv;
            out[wid * NCO + lane * 4 + 1] = e1 * inv;
            out[wid * NCO + lane * 4 + 2] = e2 * inv;
            out[wid * NCO + lane * 4 + 3] = e3 * inv;
            if (t == 0) g_ctr = 0;       // reset for next graph replay
        }
    }
}

// ---------------------------------------------------------------------------
extern "C" void kernel_launch(void* const* d_in, const int* in_sizes, int n_in,
                              void* d_out, int out_size)
{
    const float* act   = (const float*)d_in[0];
    const float* pose  = (const float*)d_in[1];
    const float* trans = (const float*)d_in[2];
    const float* ba    = (const float*)d_in[3];
    const float* bb    = (const float*)d_in[4];
    float* out = (float*)d_out;

    // floats: staging 2*64*72=9216 + Vs 17408 + acts 256 + wsl 16 +
    //         mus/nm/Aa/Cc 256 + xS 512 + xW 4 + misc 4 = 27672 (~110.7 KB)
    const int smem = (2 * 64 * PADS + 256 * PADV + 256 + 16 + 256 + 512 + 4 + 4)
                     * (int)sizeof(float);
    cudaFuncSetAttribute(k_fused, cudaFuncAttributeMaxDynamicSharedMemorySize, smem);

    dim3 grid(2, NCO, NB);               // cluster (2,1,1) over grid.x
    k_fused<<<grid, 512, smem>>>(act, pose, trans, ba, bb, out);
}